// round 4
// baseline (speedup 1.0000x reference)
#include <cuda_runtime.h>
#include <cstdint>

// Problem constants (fixed by setup_inputs)
#define BATCH   8
#define HH      256
#define WW      256
#define NPATCH  64      // 8x8 grid of 32x32 patches
#define EPSBN   1e-5f
#define ABLK    110592  // conv_weights floats per (b,p)
#define WOFF2   36864   // offset of layer-2 dynamic weights (64*9*64)

// ---------------- scratch (static device globals; no allocation) -------------
__device__ float g_y1[(size_t)BATCH * 128 * HH * WW];  // layer-1 pre-BN output
__device__ float g_sum1[128], g_sqs1[128];
__device__ float g_sum2[128], g_sqs2[128];
__device__ float g_a1[128], g_b1[128];                 // BN1 folded scale/bias
__device__ float g_a2[128], g_b2[128];

// ---------------- packed f32x2 helpers (sm_103a) ------------------------------
__device__ __forceinline__ unsigned long long pk2(float lo, float hi) {
    unsigned long long r;
    asm("mov.b64 %0, {%1,%2};" : "=l"(r) : "f"(lo), "f"(hi));
    return r;
}
__device__ __forceinline__ unsigned long long fma2(unsigned long long a,
                                                   unsigned long long b,
                                                   unsigned long long c) {
    unsigned long long d;
    asm("fma.rn.f32x2 %0, %1, %2, %3;" : "=l"(d) : "l"(a), "l"(b), "l"(c));
    return d;
}
__device__ __forceinline__ void upk2(unsigned long long v, float& lo, float& hi) {
    asm("mov.b64 {%0,%1}, %2;" : "=f"(lo), "=f"(hi) : "l"(v));
}

// ---------------- kernels ----------------------------------------------------

__global__ void zero_stats_kernel() {
    int t = threadIdx.x;
    if (t < 128) {
        g_sum1[t] = 0.f; g_sqs1[t] = 0.f;
        g_sum2[t] = 0.f; g_sqs2[t] = 0.f;
    }
}

// One CTA: (b, patch, group of 32 output channels). 512 threads.
// Thread tile: 4 oc x 16 px (packed as 4 x 8 f32x2 pairs).
// CIN processed in chunks of 8 channels held in smem with a 1-halo (34x34).
template<int CIN, int WOFF, int LAYER>
__global__ void __launch_bounds__(512, 1)
conv_kernel(const float* __restrict__ xin,
            const float* __restrict__ wsh,     // shared conv weights [64,CIN,3,3]
            const float* __restrict__ cwall,   // conv_weights [B,64,ABLK]
            float* __restrict__ dout)          // used when LAYER==2
{
    __shared__ float s_in[8][34][35];      // 38080 B, stride 35 => conflict-free
    __shared__ float s_w[8 * 9 * 32];      // [ci*9+k][oc], 9216 B

    const int blk   = blockIdx.x;
    const int b     = blk >> 8;            // 256 blocks per batch
    const int rem   = blk & 255;
    const int patch = rem >> 2;
    const int oc_base = (rem & 3) << 5;    // 0,32,64,96
    const int y0 = (patch >> 3) << 5;
    const int x0 = (patch & 7) << 5;

    const int tid   = threadIdx.x;
    const int pxg   = tid & 63;
    const int row   = pxg >> 1;            // 0..31
    const int col0  = (pxg & 1) << 4;      // 0 or 16
    const int oc_loc = (tid >> 6) << 2;    // 0,4,...,28

    const float* src = (LAYER == 1) ? xin : g_y1;
    float*       dst = (LAYER == 1) ? g_y1 : dout;

    unsigned long long acc[4][8];          // 4 oc x 8 pixel-pairs
    #pragma unroll
    for (int i = 0; i < 4; ++i)
        #pragma unroll
        for (int j = 0; j < 8; ++j) acc[i][j] = 0ull;

    const size_t cw_base = (size_t)(b * NPATCH + patch) * ABLK + WOFF;

    for (int cc = 0; cc < CIN / 8; ++cc) {
        __syncthreads();
        // ---- load 8-channel input halo tile (34x34 each) ----
        for (int idx = tid; idx < 8 * 34 * 34; idx += 512) {
            int ci = idx / 1156;
            int r  = (idx - ci * 1156) / 34;
            int c  = idx - ci * 1156 - r * 34;
            int gy = y0 - 1 + r, gx = x0 - 1 + c;
            float v = 0.f;
            int cig = cc * 8 + ci;
            if ((unsigned)gy < 256u && (unsigned)gx < 256u) {
                v = src[(((size_t)b * CIN + cig) * HH + gy) * WW + gx];
                if (LAYER == 2) v = fmaxf(0.f, fmaf(g_a1[cig], v, g_b1[cig]));
            }
            s_in[ci][r][c] = v;
        }
        // ---- load weights for this oc group: layout [ci*9+k][oc] ----
        for (int idx = tid; idx < 2304; idx += 512) {
            int q  = idx >> 5;              // ci*9 + k
            int oc = idx & 31;
            int ci = q / 9, k = q - ci * 9;
            int cig = cc * 8 + ci;
            int ocA = oc_base + oc;
            float wv;
            if (ocA < 64)
                wv = wsh[((size_t)ocA * CIN + cig) * 9 + k];
            else
                wv = cwall[cw_base + ((size_t)(ocA - 64) * CIN + cig) * 9 + k];
            s_w[idx] = wv;
        }
        __syncthreads();
        // ---- packed f32x2 FMA core ----
        #pragma unroll 2
        for (int ci = 0; ci < 8; ++ci) {
            #pragma unroll
            for (int ky = 0; ky < 3; ++ky) {
                const float* ip = &s_in[ci][row + ky][col0];
                float vb[18];
                #pragma unroll
                for (int j = 0; j < 18; ++j) vb[j] = ip[j];
                unsigned long long pe[9], po[8];
                #pragma unroll
                for (int k = 0; k < 9; ++k) pe[k] = pk2(vb[2 * k], vb[2 * k + 1]);
                #pragma unroll
                for (int k = 0; k < 8; ++k) po[k] = pk2(vb[2 * k + 1], vb[2 * k + 2]);

                const int qb = ((ci * 3 + ky) * 3) << 5;
                // kx = 0 : even pairs pe[0..7]
                {
                    float4 w4 = *(const float4*)&s_w[qb + oc_loc];
                    unsigned long long wx = pk2(w4.x, w4.x), wy = pk2(w4.y, w4.y);
                    unsigned long long wz = pk2(w4.z, w4.z), ww = pk2(w4.w, w4.w);
                    #pragma unroll
                    for (int k = 0; k < 8; ++k) {
                        acc[0][k] = fma2(wx, pe[k], acc[0][k]);
                        acc[1][k] = fma2(wy, pe[k], acc[1][k]);
                        acc[2][k] = fma2(wz, pe[k], acc[2][k]);
                        acc[3][k] = fma2(ww, pe[k], acc[3][k]);
                    }
                }
                // kx = 1 : odd pairs po[0..7]
                {
                    float4 w4 = *(const float4*)&s_w[qb + 32 + oc_loc];
                    unsigned long long wx = pk2(w4.x, w4.x), wy = pk2(w4.y, w4.y);
                    unsigned long long wz = pk2(w4.z, w4.z), ww = pk2(w4.w, w4.w);
                    #pragma unroll
                    for (int k = 0; k < 8; ++k) {
                        acc[0][k] = fma2(wx, po[k], acc[0][k]);
                        acc[1][k] = fma2(wy, po[k], acc[1][k]);
                        acc[2][k] = fma2(wz, po[k], acc[2][k]);
                        acc[3][k] = fma2(ww, po[k], acc[3][k]);
                    }
                }
                // kx = 2 : even pairs shifted pe[1..8]
                {
                    float4 w4 = *(const float4*)&s_w[qb + 64 + oc_loc];
                    unsigned long long wx = pk2(w4.x, w4.x), wy = pk2(w4.y, w4.y);
                    unsigned long long wz = pk2(w4.z, w4.z), ww = pk2(w4.w, w4.w);
                    #pragma unroll
                    for (int k = 0; k < 8; ++k) {
                        acc[0][k] = fma2(wx, pe[k + 1], acc[0][k]);
                        acc[1][k] = fma2(wy, pe[k + 1], acc[1][k]);
                        acc[2][k] = fma2(wz, pe[k + 1], acc[2][k]);
                        acc[3][k] = fma2(ww, pe[k + 1], acc[3][k]);
                    }
                }
            }
        }
    }

    // ---- write out + per-channel sum/sumsq (warp-uniform oc) ----
    float* gsum = (LAYER == 1) ? g_sum1 : g_sum2;
    float* gsqs = (LAYER == 1) ? g_sqs1 : g_sqs2;
    #pragma unroll
    for (int i = 0; i < 4; ++i) {
        int oc = oc_base + oc_loc + i;
        size_t base = (((size_t)b * 128 + oc) * HH + (y0 + row)) * WW + x0 + col0;
        float ls = 0.f, lq = 0.f;
        #pragma unroll
        for (int k = 0; k < 8; ++k) {
            float v0, v1;
            upk2(acc[i][k], v0, v1);
            ls += v0; lq = fmaf(v0, v0, lq);
            ls += v1; lq = fmaf(v1, v1, lq);
            dst[base + 2 * k]     = v0;
            dst[base + 2 * k + 1] = v1;
        }
        #pragma unroll
        for (int off = 16; off; off >>= 1) {
            ls += __shfl_down_sync(0xffffffffu, ls, off);
            lq += __shfl_down_sync(0xffffffffu, lq, off);
        }
        if ((tid & 31) == 0) {
            atomicAdd(&gsum[oc], ls);
            atomicAdd(&gsqs[oc], lq);
        }
    }
}

__global__ void finalize_stats_kernel(const float* __restrict__ gamma,
                                      const float* __restrict__ beta,
                                      int layer)
{
    int c = threadIdx.x;
    if (c >= 128) return;
    const float invN = 1.f / (float)((size_t)BATCH * HH * WW);
    float s = (layer == 1) ? g_sum1[c] : g_sum2[c];
    float q = (layer == 1) ? g_sqs1[c] : g_sqs2[c];
    float m   = s * invN;
    float var = fmaf(-m, m, q * invN);
    float inv = rsqrtf(var + EPSBN);
    float a   = gamma[c] * inv;
    float bb  = fmaf(-a, m, beta[c]);
    if (layer == 1) { g_a1[c] = a; g_b1[c] = bb; }
    else            { g_a2[c] = a; g_b2[c] = bb; }
}

__global__ void apply_bn2_kernel(float4* __restrict__ out)
{
    const size_t n4 = (size_t)BATCH * 128 * HH * WW / 4;   // 16777216
    for (size_t i = (size_t)blockIdx.x * blockDim.x + threadIdx.x; i < n4;
         i += (size_t)gridDim.x * blockDim.x) {
        int c = (int)((i >> 14) & 127);                    // 16384 float4 per (b,c) image
        float a = g_a2[c], bb = g_b2[c];
        float4 v = out[i];
        v.x = fmaxf(0.f, fmaf(a, v.x, bb));
        v.y = fmaxf(0.f, fmaf(a, v.y, bb));
        v.z = fmaxf(0.f, fmaf(a, v.z, bb));
        v.w = fmaxf(0.f, fmaf(a, v.w, bb));
        out[i] = v;
    }
}

// ---------------- launcher ----------------------------------------------------
extern "C" void kernel_launch(void* const* d_in, const int* in_sizes, int n_in,
                              void* d_out, int out_size)
{
    const float* x      = (const float*)d_in[0];  // [8,64,256,256]
    const float* cw     = (const float*)d_in[1];  // [8,64,110592]
    const float* w1     = (const float*)d_in[2];  // [64,64,3,3]
    const float* w2     = (const float*)d_in[3];  // [64,128,3,3]
    const float* gamma1 = (const float*)d_in[4];
    const float* beta1  = (const float*)d_in[5];
    const float* gamma2 = (const float*)d_in[6];
    const float* beta2  = (const float*)d_in[7];
    float* out = (float*)d_out;

    zero_stats_kernel<<<1, 128>>>();

    // Layer 1: conv (shared ch 0-63, dynamic ch 64-127) -> g_y1 + stats1
    conv_kernel<64, 0, 1><<<BATCH * NPATCH * 4, 512>>>(x, w1, cw, nullptr);
    finalize_stats_kernel<<<1, 128>>>(gamma1, beta1, 1);

    // Layer 2: reads g_y1 with fused BN1+ReLU at load -> d_out (pre-BN) + stats2
    conv_kernel<128, WOFF2, 2><<<BATCH * NPATCH * 4, 512>>>(nullptr, w2, cw, out);
    finalize_stats_kernel<<<1, 128>>>(gamma2, beta2, 2);

    // BN2 + ReLU in place on d_out
    apply_bn2_kernel<<<8192, 256>>>((float4*)out);
}

// round 11
// speedup vs baseline: 2.3902x; 2.3902x over previous
#include <cuda_runtime.h>
#include <cuda_bf16.h>
#include <cstdint>

#define BATCH 8
#define EPSBN 1e-5f
#define ABLK  110592
#define WOFF2 36864

// ---------------- scratch globals (~483 MB) ------------------------------------
__device__ float g_y1[(size_t)8 * 128 * 256 * 256];            // 256 MB
__device__ float g_sum1[128], g_sqs1[128], g_sum2[128], g_sqs2[128];
__device__ float g_a1[128], g_b1[128], g_a2[128], g_b2[128];

// shared-weight tiles (ONE copy): [tap*NS+sub][64 oc][32 ci]
__device__ __align__(16) __nv_bfloat16 g_wsh1hi[18 * 2048], g_wsh1lo[18 * 2048];
__device__ __align__(16) __nv_bfloat16 g_wsh2hi[36 * 2048], g_wsh2lo[36 * 2048];
// dynamic-weight tiles: [bp][tap*NS+sub][64 oc][32 ci]
__device__ __align__(16) __nv_bfloat16 g_wdy1hi[(size_t)512 * 18 * 2048];
__device__ __align__(16) __nv_bfloat16 g_wdy1lo[(size_t)512 * 18 * 2048];
__device__ __align__(16) __nv_bfloat16 g_wdy2hi[(size_t)512 * 36 * 2048];
__device__ __align__(16) __nv_bfloat16 g_wdy2lo[(size_t)512 * 36 * 2048];

// ---------------- helpers -------------------------------------------------------
#define MMA(d, a, b0, b1) \
    asm volatile("mma.sync.aligned.m16n8k16.row.col.f32.bf16.bf16.f32 " \
                 "{%0,%1,%2,%3},{%4,%5,%6,%7},{%8,%9},{%0,%1,%2,%3};" \
                 : "+f"((d)[0]), "+f"((d)[1]), "+f"((d)[2]), "+f"((d)[3]) \
                 : "r"((a)[0]), "r"((a)[1]), "r"((a)[2]), "r"((a)[3]), "r"(b0), "r"(b1))

// static smem: A [2 split][128 px][80B], W [2 split][128 oc][80B]
static constexpr int A_SPLIT = 10240;
static constexpr int OFF_W   = 20480;
static constexpr int W_SPLIT = 10240;
static constexpr int SMEM_TOTAL = 40960;

// ---------------- small kernels -------------------------------------------------
__global__ void zero_stats_kernel() {
    int t = threadIdx.x;
    if (t < 128) { g_sum1[t] = 0.f; g_sqs1[t] = 0.f; g_sum2[t] = 0.f; g_sqs2[t] = 0.f; }
}

// shared weights [64oc][CIN][9] -> tiles [k*NS+sub][64][32]
template<int CIN, int LAYER>
__global__ void wprep_sh_kernel(const float* __restrict__ wsh)
{
    int idx = blockIdx.x * 256 + threadIdx.x;
    if (idx >= 64 * CIN) return;
    int ci = idx & (CIN - 1);
    int oc = idx >> ((CIN == 64) ? 6 : 7);
    constexpr int NS = CIN / 32;
    int sub = ci >> 5, cl = ci & 31;
    const float* s = wsh + ((size_t)oc * CIN + ci) * 9;
    __nv_bfloat16* hi = (LAYER == 1) ? g_wsh1hi : g_wsh2hi;   // device-code symbol
    __nv_bfloat16* lo = (LAYER == 1) ? g_wsh1lo : g_wsh2lo;
    #pragma unroll
    for (int k = 0; k < 9; ++k) {
        float v = s[k];
        __nv_bfloat16 hb = __float2bfloat16(v);
        size_t off = (size_t)(k * NS + sub) * 2048 + oc * 32 + cl;
        hi[off] = hb;
        lo[off] = __float2bfloat16(v - __bfloat162float(hb));
    }
}

// dynamic weights -> tiles [bp][k*NS+sub][64][32]
template<int CIN, int WOFF, int LAYER>
__global__ void wprep_dy_kernel(const float* __restrict__ cw)
{
    const long long idx = (long long)blockIdx.x * 256 + threadIdx.x;
    constexpr int LC = (CIN == 64) ? 6 : 7;
    const int ci = (int)(idx & (CIN - 1));
    const int oc = (int)((idx >> LC) & 63);
    const int bp = (int)(idx >> (LC + 6));
    constexpr int NS = CIN / 32;
    const int sub = ci >> 5, cl = ci & 31;
    const float* s = cw + (size_t)bp * ABLK + WOFF + ((size_t)oc * CIN + ci) * 9;
    __nv_bfloat16* hi = (LAYER == 1) ? g_wdy1hi : g_wdy2hi;   // device-code symbol
    __nv_bfloat16* lo = (LAYER == 1) ? g_wdy1lo : g_wdy2lo;
    #pragma unroll
    for (int k = 0; k < 9; ++k) {
        float v = s[k];
        __nv_bfloat16 hb = __float2bfloat16(v);
        size_t off = ((size_t)bp * (9 * NS) + k * NS + sub) * 2048 + oc * 32 + cl;
        hi[off] = hb;
        lo[off] = __float2bfloat16(v - __bfloat162float(hb));
    }
}

// ---------------- main conv: bf16-split warp-MMA implicit GEMM -------------------
// CTA = (b, patch, 4-row quad). D[128 px][128 oc]; 8 warps x (64px x 32oc).
// ALL device globals resolved INSIDE device code (the R6-R10 bug was passing
// __device__ symbols as host-side kernel arguments -> ATS-read zeros on GB300).
template<int CIN, int LAYER>
__global__ void __launch_bounds__(256, 2)
conv_mma_kernel(const float* __restrict__ xin,     // harness pointer (L1 only)
                float* __restrict__ dout)          // harness pointer (L2 only)
{
    __shared__ __align__(16) unsigned char sm[SMEM_TOTAL];
    const int tid = threadIdx.x, lane = tid & 31, wid = tid >> 5;
    const int wm = wid & 1, wn = wid >> 1;

    // device-code selection of all global scratch
    const float* src = (LAYER == 1) ? xin : (const float*)g_y1;
    float*       dst = (LAYER == 1) ? (float*)g_y1 : dout;
    const __nv_bfloat16* wshhi = (LAYER == 1) ? g_wsh1hi : g_wsh2hi;
    const __nv_bfloat16* wshlo = (LAYER == 1) ? g_wsh1lo : g_wsh2lo;
    const __nv_bfloat16* wdyhi = (LAYER == 1) ? g_wdy1hi : g_wdy2hi;
    const __nv_bfloat16* wdylo = (LAYER == 1) ? g_wdy1lo : g_wdy2lo;

    const int blk = blockIdx.x;
    const int b = blk >> 9, p = (blk >> 3) & 63, q = blk & 7;
    const int y0 = ((p >> 3) << 5) + (q << 2);     // 4 output rows = 128 px
    const int x0 = (p & 7) << 5;
    const int bp = b * 64 + p;
    constexpr int NS = CIN / 32;
    constexpr int NC = 9 * NS;

    float d[4][4][4];
    #pragma unroll
    for (int i = 0; i < 4; ++i)
        #pragma unroll
        for (int j = 0; j < 4; ++j)
            #pragma unroll
            for (int k = 0; k < 4; ++k) d[i][j][k] = 0.f;

    const int r4 = lane >> 2;            // 0..7
    const int kb = (lane & 3) * 4;       // byte offset of this thread's k-pair

    for (int cc = 0; cc < NC; ++cc) {
        const int tap = cc / NS, sub = cc - tap * NS;
        const int ky = tap / 3, kx = tap - ky * 3;

        // ---- W tiles via plain LDG -> STS: rows 0-63 shared, 64-127 dynamic ----
        #pragma unroll
        for (int s = 0; s < 2; ++s) {
            const __nv_bfloat16* shp = s ? wshlo : wshhi;
            const __nv_bfloat16* dyp = s ? wdylo : wdyhi;
            #pragma unroll
            for (int t = 0; t < 2; ++t) {
                int i = tid + t * 256;           // 0..511
                int row = i >> 2, c4 = i & 3;
                const uint4* gsrc = (row < 64)
                    ? (const uint4*)((const char*)(shp + (size_t)cc * 2048)
                                     + row * 64 + c4 * 16)
                    : (const uint4*)((const char*)(dyp + ((size_t)bp * NC + cc) * 2048)
                                     + (row - 64) * 64 + c4 * 16);
                *(uint4*)(sm + OFF_W + s * W_SPLIT + row * 80 + c4 * 16) = *gsrc;
            }
        }

        // ---- A tile: guarded fp32 loads, BN1+ReLU (L2), hi/lo split, STS ----
        #pragma unroll
        for (int it = 0; it < 16; ++it) {
            int pair = it * 8 + wid;             // 0..127 = (rquad, ci)
            int rq = pair >> 5, ci = pair & 31;
            int y = y0 + rq + ky - 1;
            int x = x0 + lane + kx - 1;
            int c = sub * 32 + ci;
            float v = 0.f;
            if ((unsigned)y < 256u && (unsigned)x < 256u) {
                v = src[(((size_t)(b * CIN + c)) << 16) + (y << 8) + x];
                if (LAYER == 2) v = fmaxf(0.f, fmaf(g_a1[c], v, g_b1[c]));
            }
            __nv_bfloat16 hb = __float2bfloat16(v);
            float hv = __bfloat162float(hb);
            uint32_t off = (uint32_t)(rq * 32 + lane) * 80 + ci * 2;
            *(__nv_bfloat16*)(sm + off) = hb;
            *(__nv_bfloat16*)(sm + A_SPLIT + off) = __float2bfloat16(v - hv);
        }
        __syncthreads();

        // ---- compute: D += Ah*Wh + Ah*Wl + Al*Wh (fragments via LDS.32) ----
        const unsigned char* Asm = sm + wm * 5120;           // 64 px rows
        const unsigned char* Wsm = sm + OFF_W + wn * 2560;   // 32 oc rows
        #pragma unroll
        for (int ks = 0; ks < 2; ++ks) {
            const int ko = ks * 32 + kb;
            uint32_t a[4][4], w0[4], w1[4], v0[4], v1[4];
            // A-hi fragments
            #pragma unroll
            for (int mf = 0; mf < 4; ++mf) {
                const unsigned char* ap = Asm + (mf * 16 + r4) * 80 + ko;
                a[mf][0] = *(const uint32_t*)(ap);
                a[mf][1] = *(const uint32_t*)(ap + 8 * 80);
                a[mf][2] = *(const uint32_t*)(ap + 16);
                a[mf][3] = *(const uint32_t*)(ap + 8 * 80 + 16);
            }
            // W-hi fragments
            #pragma unroll
            for (int n8 = 0; n8 < 4; ++n8) {
                const unsigned char* wp = Wsm + (n8 * 8 + r4) * 80 + ko;
                w0[n8] = *(const uint32_t*)(wp);
                w1[n8] = *(const uint32_t*)(wp + 16);
            }
            #pragma unroll
            for (int mf = 0; mf < 4; ++mf)
                #pragma unroll
                for (int n8 = 0; n8 < 4; ++n8)
                    MMA(d[mf][n8], a[mf], w0[n8], w1[n8]);
            // W-lo fragments, Ah * Wl
            #pragma unroll
            for (int n8 = 0; n8 < 4; ++n8) {
                const unsigned char* wp = Wsm + W_SPLIT + (n8 * 8 + r4) * 80 + ko;
                v0[n8] = *(const uint32_t*)(wp);
                v1[n8] = *(const uint32_t*)(wp + 16);
            }
            #pragma unroll
            for (int mf = 0; mf < 4; ++mf)
                #pragma unroll
                for (int n8 = 0; n8 < 4; ++n8)
                    MMA(d[mf][n8], a[mf], v0[n8], v1[n8]);
            // A-lo fragments, Al * Wh
            #pragma unroll
            for (int mf = 0; mf < 4; ++mf) {
                const unsigned char* ap = Asm + A_SPLIT + (mf * 16 + r4) * 80 + ko;
                a[mf][0] = *(const uint32_t*)(ap);
                a[mf][1] = *(const uint32_t*)(ap + 8 * 80);
                a[mf][2] = *(const uint32_t*)(ap + 16);
                a[mf][3] = *(const uint32_t*)(ap + 8 * 80 + 16);
            }
            #pragma unroll
            for (int mf = 0; mf < 4; ++mf)
                #pragma unroll
                for (int n8 = 0; n8 < 4; ++n8)
                    MMA(d[mf][n8], a[mf], w0[n8], w1[n8]);
        }
        __syncthreads();
    }

    // ---- epilogue: c-frag -> [b][oc][y][x] ----
    const int c2 = (lane & 3) << 1;
    #pragma unroll
    for (int mf = 0; mf < 4; ++mf) {
        int pxA = wm * 64 + mf * 16 + r4;
        int pxB = pxA + 8;
        size_t pixA = (size_t)(y0 + (pxA >> 5)) * 256 + x0 + (pxA & 31);
        size_t pixB = (size_t)(y0 + (pxB >> 5)) * 256 + x0 + (pxB & 31);
        #pragma unroll
        for (int n8 = 0; n8 < 4; ++n8) {
            int oc = wn * 32 + n8 * 8 + c2;
            size_t base = ((size_t)(b * 128 + oc)) << 16;
            dst[base + pixA]         = d[mf][n8][0];
            dst[base + 65536 + pixA] = d[mf][n8][1];
            dst[base + pixB]         = d[mf][n8][2];
            dst[base + 65536 + pixB] = d[mf][n8][3];
        }
    }
}

// ---------------- BN stats / finalize / apply -----------------------------------
template<int LAYER>
__global__ void stats_kernel(const float4* __restrict__ dout)
{
    __shared__ float ss[8], sq[8];
    const float4* src = (LAYER == 1) ? (const float4*)g_y1 : dout;
    const int c = blockIdx.x & 127;
    const float4* ptr = src + (size_t)blockIdx.x * 16384;
    float s = 0.f, qv = 0.f;
    for (int i = threadIdx.x; i < 16384; i += 256) {
        float4 v = ptr[i];
        s += v.x + v.y + v.z + v.w;
        qv = fmaf(v.x, v.x, qv); qv = fmaf(v.y, v.y, qv);
        qv = fmaf(v.z, v.z, qv); qv = fmaf(v.w, v.w, qv);
    }
    #pragma unroll
    for (int o = 16; o; o >>= 1) {
        s  += __shfl_down_sync(0xffffffffu, s, o);
        qv += __shfl_down_sync(0xffffffffu, qv, o);
    }
    if ((threadIdx.x & 31) == 0) { ss[threadIdx.x >> 5] = s; sq[threadIdx.x >> 5] = qv; }
    __syncthreads();
    if (threadIdx.x == 0) {
        float S = 0.f, Q = 0.f;
        #pragma unroll
        for (int w = 0; w < 8; ++w) { S += ss[w]; Q += sq[w]; }
        atomicAdd((LAYER == 1) ? &g_sum1[c] : &g_sum2[c], S);
        atomicAdd((LAYER == 1) ? &g_sqs1[c] : &g_sqs2[c], Q);
    }
}

__global__ void finalize_stats_kernel(const float* __restrict__ gamma,
                                      const float* __restrict__ beta, int layer)
{
    int c = threadIdx.x;
    if (c >= 128) return;
    const float invN = 1.f / (float)((size_t)BATCH * 256 * 256);
    float s = (layer == 1) ? g_sum1[c] : g_sum2[c];
    float q = (layer == 1) ? g_sqs1[c] : g_sqs2[c];
    float m = s * invN;
    float var = fmaf(-m, m, q * invN);
    float inv = rsqrtf(var + EPSBN);
    float a = gamma[c] * inv;
    float bb = fmaf(-a, m, beta[c]);
    if (layer == 1) { g_a1[c] = a; g_b1[c] = bb; }
    else            { g_a2[c] = a; g_b2[c] = bb; }
}

__global__ void apply_bn2_kernel(float4* __restrict__ out)
{
    const size_t n4 = (size_t)BATCH * 128 * 256 * 256 / 4;
    for (size_t i = (size_t)blockIdx.x * blockDim.x + threadIdx.x; i < n4;
         i += (size_t)gridDim.x * blockDim.x) {
        int c = (int)((i >> 14) & 127);
        float a = g_a2[c], bb = g_b2[c];
        float4 v = out[i];
        v.x = fmaxf(0.f, fmaf(a, v.x, bb));
        v.y = fmaxf(0.f, fmaf(a, v.y, bb));
        v.z = fmaxf(0.f, fmaf(a, v.z, bb));
        v.w = fmaxf(0.f, fmaf(a, v.w, bb));
        out[i] = v;
    }
}

// ---------------- launcher (harness pointers ONLY as kernel args) ----------------
extern "C" void kernel_launch(void* const* d_in, const int* in_sizes, int n_in,
                              void* d_out, int out_size)
{
    const float* x      = (const float*)d_in[0];
    const float* cw     = (const float*)d_in[1];
    const float* w1     = (const float*)d_in[2];
    const float* w2     = (const float*)d_in[3];
    const float* gamma1 = (const float*)d_in[4];
    const float* beta1  = (const float*)d_in[5];
    const float* gamma2 = (const float*)d_in[6];
    const float* beta2  = (const float*)d_in[7];
    float* out = (float*)d_out;

    zero_stats_kernel<<<1, 128>>>();
    wprep_sh_kernel<64, 1><<<16, 256>>>(w1);
    wprep_sh_kernel<128, 2><<<32, 256>>>(w2);
    wprep_dy_kernel<64, 0, 1><<<8192, 256>>>(cw);
    wprep_dy_kernel<128, WOFF2, 2><<<16384, 256>>>(cw);

    // layer 1: x -> g_y1 (pre-BN)
    conv_mma_kernel<64, 1><<<4096, 256>>>(x, nullptr);
    stats_kernel<1><<<1024, 256>>>(nullptr);
    finalize_stats_kernel<<<1, 128>>>(gamma1, beta1, 1);

    // layer 2: g_y1 (BN1+ReLU fused in loader) -> out (pre-BN)
    conv_mma_kernel<128, 2><<<4096, 256>>>(nullptr, out);
    stats_kernel<2><<<1024, 256>>>((const float4*)out);
    finalize_stats_kernel<<<1, 128>>>(gamma2, beta2, 2);

    apply_bn2_kernel<<<8192, 256>>>((float4*)out);
}

// round 12
// speedup vs baseline: 2.9540x; 1.2359x over previous
#include <cuda_runtime.h>
#include <cuda_bf16.h>
#include <cstdint>

#define BATCH 8
#define EPSBN 1e-5f
#define ABLK  110592
#define WOFF2 36864
#define PW    258            // padded width (1-px halo each side)

// ---------------- scratch globals (all referenced ONLY in device code) ----------
__device__ float g_y1[(size_t)8 * 128 * 256 * 256];            // 256 MB
__device__ float g_sum1[128], g_sqs1[128], g_sum2[128], g_sqs2[128];
__device__ float g_a1[128], g_b1[128], g_a2[128], g_b2[128];

// padded split activations [b][y+1][x+1][ci] bf16
__device__ __align__(16) __nv_bfloat16 g_x1hi[(size_t)8 * PW * PW * 64];
__device__ __align__(16) __nv_bfloat16 g_x1lo[(size_t)8 * PW * PW * 64];
__device__ __align__(16) __nv_bfloat16 g_x2hi[(size_t)8 * PW * PW * 128];
__device__ __align__(16) __nv_bfloat16 g_x2lo[(size_t)8 * PW * PW * 128];
// weight tiles, k-chunk 16: [(k*NS)+sub][64 oc][16 ci]
__device__ __align__(16) __nv_bfloat16 g_wsh1hi[36 * 1024], g_wsh1lo[36 * 1024];
__device__ __align__(16) __nv_bfloat16 g_wsh2hi[72 * 1024], g_wsh2lo[72 * 1024];
__device__ __align__(16) __nv_bfloat16 g_wdy1hi[(size_t)512 * 36 * 1024];
__device__ __align__(16) __nv_bfloat16 g_wdy1lo[(size_t)512 * 36 * 1024];
__device__ __align__(16) __nv_bfloat16 g_wdy2hi[(size_t)512 * 72 * 1024];
__device__ __align__(16) __nv_bfloat16 g_wdy2lo[(size_t)512 * 72 * 1024];

// ---------------- helpers -------------------------------------------------------
#define MMA(d, a, b0, b1) \
    asm volatile("mma.sync.aligned.m16n8k16.row.col.f32.bf16.bf16.f32 " \
                 "{%0,%1,%2,%3},{%4,%5,%6,%7},{%8,%9},{%0,%1,%2,%3};" \
                 : "+f"((d)[0]), "+f"((d)[1]), "+f"((d)[2]), "+f"((d)[3]) \
                 : "r"((a)[0]), "r"((a)[1]), "r"((a)[2]), "r"((a)[3]), "r"(b0), "r"(b1))

__device__ __forceinline__ uint32_t pkbf(float lo, float hi) {
    return (uint32_t)__bfloat16_as_ushort(__float2bfloat16(lo)) |
           ((uint32_t)__bfloat16_as_ushort(__float2bfloat16(hi)) << 16);
}

// static smem: A [2 split][128 px][48B], W [2 split][128 oc][48B]
static constexpr int A_SPLIT = 6144;
static constexpr int OFF_W   = 12288;
static constexpr int W_SPLIT = 6144;
static constexpr int SMEM_TOTAL = 24576;

// ---------------- small kernels -------------------------------------------------
__global__ void zero_stats_kernel() {
    int t = threadIdx.x;
    if (t < 128) { g_sum1[t] = 0.f; g_sqs1[t] = 0.f; g_sum2[t] = 0.f; g_sqs2[t] = 0.f; }
}

__global__ void zero_border_kernel() {
    int idx = blockIdx.x * 256 + threadIdx.x;
    if (idx >= 8 * 1028) return;
    int b = idx / 1028, s = idx % 1028;
    int y, x;
    if (s < 258)      { y = 0;           x = s; }
    else if (s < 516) { y = 257;         x = s - 258; }
    else if (s < 772) { y = s - 516 + 1; x = 0; }
    else              { y = s - 772 + 1; x = 257; }
    size_t p = ((size_t)b * PW + y) * PW + x;
    uint4 z = make_uint4(0, 0, 0, 0);
    uint4* h1 = (uint4*)(g_x1hi + p * 64);
    uint4* l1 = (uint4*)(g_x1lo + p * 64);
    #pragma unroll
    for (int i = 0; i < 8; ++i) { h1[i] = z; l1[i] = z; }
    uint4* h2 = (uint4*)(g_x2hi + p * 128);
    uint4* l2 = (uint4*)(g_x2lo + p * 128);
    #pragma unroll
    for (int i = 0; i < 16; ++i) { h2[i] = z; l2[i] = z; }
}

// x -> padded [b][y+1][x+1][ci] bf16 hi/lo; layer 2 applies BN1+ReLU
template<int CIN, int LAYER>
__global__ void xsplit_kernel(const float* __restrict__ xin)
{
    __shared__ float tile[CIN][65];
    const int blk = blockIdx.x;
    const int xb = blk & 3, y = (blk >> 2) & 255, b = blk >> 10;
    const int tid = threadIdx.x;
    const float* src = (LAYER == 1) ? xin : (const float*)g_y1;
    __nv_bfloat16* dhi = (LAYER == 1) ? g_x1hi : g_x2hi;
    __nv_bfloat16* dlo = (LAYER == 1) ? g_x1lo : g_x2lo;

    for (int i = tid; i < CIN * 64; i += 256) {
        int c = i >> 6, x = i & 63;
        float v = src[(((size_t)(b * CIN + c)) << 16) + (y << 8) + (xb << 6) + x];
        if (LAYER == 2) v = fmaxf(0.f, fmaf(g_a1[c], v, g_b1[c]));
        tile[c][x] = v;
    }
    __syncthreads();

    const int GSH = (CIN == 64) ? 3 : 4;
    const int GP  = CIN / 8;
    for (int i = tid; i < 64 * GP; i += 256) {
        int x = i >> GSH, g = i & (GP - 1);
        float v[8], hv[8];
        #pragma unroll
        for (int j = 0; j < 8; ++j) {
            v[j]  = tile[g * 8 + j][x];
            hv[j] = __bfloat162float(__float2bfloat16(v[j]));
        }
        uint4 uh, ul;
        uh.x = pkbf(hv[0], hv[1]); uh.y = pkbf(hv[2], hv[3]);
        uh.z = pkbf(hv[4], hv[5]); uh.w = pkbf(hv[6], hv[7]);
        ul.x = pkbf(v[0] - hv[0], v[1] - hv[1]); ul.y = pkbf(v[2] - hv[2], v[3] - hv[3]);
        ul.z = pkbf(v[4] - hv[4], v[5] - hv[5]); ul.w = pkbf(v[6] - hv[6], v[7] - hv[7]);
        size_t off = (((size_t)b * PW + (y + 1)) * PW + (xb * 64 + x + 1)) * CIN + g * 8;
        *(uint4*)((char*)dhi + off * 2) = uh;
        *(uint4*)((char*)dlo + off * 2) = ul;
    }
}

// shared weights [64oc][CIN][9] -> tiles [k*NS+sub][64][16]
template<int CIN, int LAYER>
__global__ void wprep_sh_kernel(const float* __restrict__ wsh)
{
    int idx = blockIdx.x * 256 + threadIdx.x;
    if (idx >= 64 * CIN) return;
    int ci = idx & (CIN - 1);
    int oc = idx >> ((CIN == 64) ? 6 : 7);
    constexpr int NS = CIN / 16;
    int sub = ci >> 4, cl = ci & 15;
    const float* s = wsh + ((size_t)oc * CIN + ci) * 9;
    __nv_bfloat16* hi = (LAYER == 1) ? g_wsh1hi : g_wsh2hi;
    __nv_bfloat16* lo = (LAYER == 1) ? g_wsh1lo : g_wsh2lo;
    #pragma unroll
    for (int k = 0; k < 9; ++k) {
        float v = s[k];
        __nv_bfloat16 hb = __float2bfloat16(v);
        size_t off = (size_t)(k * NS + sub) * 1024 + oc * 16 + cl;
        hi[off] = hb;
        lo[off] = __float2bfloat16(v - __bfloat162float(hb));
    }
}

// dynamic weights -> tiles [bp][k*NS+sub][64][16]
template<int CIN, int WOFF, int LAYER>
__global__ void wprep_dy_kernel(const float* __restrict__ cw)
{
    const long long idx = (long long)blockIdx.x * 256 + threadIdx.x;
    constexpr int LC = (CIN == 64) ? 6 : 7;
    const int ci = (int)(idx & (CIN - 1));
    const int oc = (int)((idx >> LC) & 63);
    const int bp = (int)(idx >> (LC + 6));
    constexpr int NS = CIN / 16;
    const int sub = ci >> 4, cl = ci & 15;
    const float* s = cw + (size_t)bp * ABLK + WOFF + ((size_t)oc * CIN + ci) * 9;
    __nv_bfloat16* hi = (LAYER == 1) ? g_wdy1hi : g_wdy2hi;
    __nv_bfloat16* lo = (LAYER == 1) ? g_wdy1lo : g_wdy2lo;
    #pragma unroll
    for (int k = 0; k < 9; ++k) {
        float v = s[k];
        __nv_bfloat16 hb = __float2bfloat16(v);
        size_t off = ((size_t)bp * (9 * NS) + k * NS + sub) * 1024 + oc * 16 + cl;
        hi[off] = hb;
        lo[off] = __float2bfloat16(v - __bfloat162float(hb));
    }
}

// ---------------- main conv: bf16-split warp-MMA, register-double-buffered -------
// CTA = (b, patch, 4-row quad). D[128 px][128 oc]; 8 warps x (64px x 32oc).
template<int CIN, int LAYER>
__global__ void __launch_bounds__(256, 2)
conv_mma_kernel(float* __restrict__ dout)
{
    __shared__ __align__(16) unsigned char sm[SMEM_TOTAL];
    const int tid = threadIdx.x, lane = tid & 31, wid = tid >> 5;
    const int wm = wid & 1, wn = wid >> 1;

    const __nv_bfloat16* xhi = (LAYER == 1) ? g_x1hi : g_x2hi;
    const __nv_bfloat16* xlo = (LAYER == 1) ? g_x1lo : g_x2lo;
    const __nv_bfloat16* wshhi = (LAYER == 1) ? g_wsh1hi : g_wsh2hi;
    const __nv_bfloat16* wshlo = (LAYER == 1) ? g_wsh1lo : g_wsh2lo;
    const __nv_bfloat16* wdyhi = (LAYER == 1) ? g_wdy1hi : g_wdy2hi;
    const __nv_bfloat16* wdylo = (LAYER == 1) ? g_wdy1lo : g_wdy2lo;
    float* dst = (LAYER == 1) ? (float*)g_y1 : dout;

    const int blk = blockIdx.x;
    const int b = blk >> 9, p = (blk >> 3) & 63, q = blk & 7;
    const int y0 = ((p >> 3) << 5) + (q << 2);
    const int x0 = (p & 7) << 5;
    const int bp = b * 64 + p;
    constexpr int NS = CIN / 16;
    constexpr int NC = 9 * NS;

    float d[4][4][4];
    #pragma unroll
    for (int i = 0; i < 4; ++i)
        #pragma unroll
        for (int j = 0; j < 4; ++j)
            #pragma unroll
            for (int k = 0; k < 4; ++k) d[i][j][k] = 0.f;

    const int r4 = lane >> 2;
    const int kb = (lane & 3) * 4;
    const int px = tid >> 1, seg = tid & 1;    // this thread's A row / 16B seg
    const int wrow = tid >> 1;                 // this thread's W row

    uint4 pfA[2], pfW[2];                      // [split]

    auto prefetch = [&](int cc) {
        const int tap = cc / NS, sub = cc - tap * NS;
        const int ky = tap / 3, kx = tap - ky * 3;
        const int y = y0 + (px >> 5) + ky;     // padded coords
        const int x = x0 + (px & 31) + kx;
        const size_t aoff = (((size_t)b * PW + y) * PW + x) * CIN + sub * 16 + seg * 8;
        pfA[0] = *(const uint4*)(xhi + aoff);
        pfA[1] = *(const uint4*)(xlo + aoff);
        if (wrow < 64) {
            const size_t woff = (size_t)cc * 1024 + wrow * 16 + seg * 8;
            pfW[0] = *(const uint4*)(wshhi + woff);
            pfW[1] = *(const uint4*)(wshlo + woff);
        } else {
            const size_t woff = ((size_t)bp * NC + cc) * 1024 + (wrow - 64) * 16 + seg * 8;
            pfW[0] = *(const uint4*)(wdyhi + woff);
            pfW[1] = *(const uint4*)(wdylo + woff);
        }
    };

    prefetch(0);
    for (int cc = 0; cc < NC; ++cc) {
        __syncthreads();                       // previous compute done reading smem
        *(uint4*)(sm + px * 48 + seg * 16)              = pfA[0];
        *(uint4*)(sm + A_SPLIT + px * 48 + seg * 16)    = pfA[1];
        *(uint4*)(sm + OFF_W + wrow * 48 + seg * 16)            = pfW[0];
        *(uint4*)(sm + OFF_W + W_SPLIT + wrow * 48 + seg * 16)  = pfW[1];
        __syncthreads();
        if (cc + 1 < NC) prefetch(cc + 1);     // LDG in flight during compute

        const unsigned char* Asm = sm + wm * 3072;          // 64 px rows
        const unsigned char* Wsm = sm + OFF_W + wn * 1536;  // 32 oc rows
        uint32_t a[4][4], w0[4], w1[4], v0[4], v1[4];
        // A-hi fragments
        #pragma unroll
        for (int mf = 0; mf < 4; ++mf) {
            const unsigned char* ap = Asm + (mf * 16 + r4) * 48 + kb;
            a[mf][0] = *(const uint32_t*)(ap);
            a[mf][1] = *(const uint32_t*)(ap + 384);
            a[mf][2] = *(const uint32_t*)(ap + 16);
            a[mf][3] = *(const uint32_t*)(ap + 400);
        }
        // W-hi fragments
        #pragma unroll
        for (int n8 = 0; n8 < 4; ++n8) {
            const unsigned char* wp = Wsm + (n8 * 8 + r4) * 48 + kb;
            w0[n8] = *(const uint32_t*)(wp);
            w1[n8] = *(const uint32_t*)(wp + 16);
        }
        #pragma unroll
        for (int mf = 0; mf < 4; ++mf)
            #pragma unroll
            for (int n8 = 0; n8 < 4; ++n8)
                MMA(d[mf][n8], a[mf], w0[n8], w1[n8]);
        // Ah * Wl
        #pragma unroll
        for (int n8 = 0; n8 < 4; ++n8) {
            const unsigned char* wp = Wsm + W_SPLIT + (n8 * 8 + r4) * 48 + kb;
            v0[n8] = *(const uint32_t*)(wp);
            v1[n8] = *(const uint32_t*)(wp + 16);
        }
        #pragma unroll
        for (int mf = 0; mf < 4; ++mf)
            #pragma unroll
            for (int n8 = 0; n8 < 4; ++n8)
                MMA(d[mf][n8], a[mf], v0[n8], v1[n8]);
        // Al * Wh
        #pragma unroll
        for (int mf = 0; mf < 4; ++mf) {
            const unsigned char* ap = Asm + A_SPLIT + (mf * 16 + r4) * 48 + kb;
            a[mf][0] = *(const uint32_t*)(ap);
            a[mf][1] = *(const uint32_t*)(ap + 384);
            a[mf][2] = *(const uint32_t*)(ap + 16);
            a[mf][3] = *(const uint32_t*)(ap + 400);
        }
        #pragma unroll
        for (int mf = 0; mf < 4; ++mf)
            #pragma unroll
            for (int n8 = 0; n8 < 4; ++n8)
                MMA(d[mf][n8], a[mf], w0[n8], w1[n8]);
    }

    // ---- epilogue: store + fused BN stats ----
    float* gsum = (LAYER == 1) ? g_sum1 : g_sum2;
    float* gsqs = (LAYER == 1) ? g_sqs1 : g_sqs2;
    const int c2 = (lane & 3) << 1;
    #pragma unroll
    for (int mf = 0; mf < 4; ++mf) {
        int pxA = wm * 64 + mf * 16 + r4;
        int pxB = pxA + 8;
        size_t pixA = (size_t)(y0 + (pxA >> 5)) * 256 + x0 + (pxA & 31);
        size_t pixB = (size_t)(y0 + (pxB >> 5)) * 256 + x0 + (pxB & 31);
        #pragma unroll
        for (int n8 = 0; n8 < 4; ++n8) {
            int oc = wn * 32 + n8 * 8 + c2;
            size_t base = ((size_t)(b * 128 + oc)) << 16;
            dst[base + pixA]         = d[mf][n8][0];
            dst[base + 65536 + pixA] = d[mf][n8][1];
            dst[base + pixB]         = d[mf][n8][2];
            dst[base + 65536 + pixB] = d[mf][n8][3];
        }
    }
    #pragma unroll
    for (int n8 = 0; n8 < 4; ++n8) {
        float sA = 0.f, qA = 0.f, sB = 0.f, qB = 0.f;
        #pragma unroll
        for (int mf = 0; mf < 4; ++mf) {
            float e0 = d[mf][n8][0], e1 = d[mf][n8][1];
            float e2 = d[mf][n8][2], e3 = d[mf][n8][3];
            sA += e0 + e2; qA = fmaf(e0, e0, fmaf(e2, e2, qA));
            sB += e1 + e3; qB = fmaf(e1, e1, fmaf(e3, e3, qB));
        }
        #pragma unroll
        for (int off = 16; off >= 4; off >>= 1) {
            sA += __shfl_down_sync(0xffffffffu, sA, off);
            qA += __shfl_down_sync(0xffffffffu, qA, off);
            sB += __shfl_down_sync(0xffffffffu, sB, off);
            qB += __shfl_down_sync(0xffffffffu, qB, off);
        }
        if (lane < 4) {
            int oc = wn * 32 + n8 * 8 + c2;
            atomicAdd(&gsum[oc], sA);     atomicAdd(&gsqs[oc], qA);
            atomicAdd(&gsum[oc + 1], sB); atomicAdd(&gsqs[oc + 1], qB);
        }
    }
}

// ---------------- BN finalize / apply -------------------------------------------
__global__ void finalize_stats_kernel(const float* __restrict__ gamma,
                                      const float* __restrict__ beta, int layer)
{
    int c = threadIdx.x;
    if (c >= 128) return;
    const float invN = 1.f / (float)((size_t)BATCH * 256 * 256);
    float s = (layer == 1) ? g_sum1[c] : g_sum2[c];
    float q = (layer == 1) ? g_sqs1[c] : g_sqs2[c];
    float m = s * invN;
    float var = fmaf(-m, m, q * invN);
    float inv = rsqrtf(var + EPSBN);
    float a = gamma[c] * inv;
    float bb = fmaf(-a, m, beta[c]);
    if (layer == 1) { g_a1[c] = a; g_b1[c] = bb; }
    else            { g_a2[c] = a; g_b2[c] = bb; }
}

__global__ void apply_bn2_kernel(float4* __restrict__ out)
{
    const size_t n4 = (size_t)BATCH * 128 * 256 * 256 / 4;
    for (size_t i = (size_t)blockIdx.x * blockDim.x + threadIdx.x; i < n4;
         i += (size_t)gridDim.x * blockDim.x) {
        int c = (int)((i >> 14) & 127);
        float a = g_a2[c], bb = g_b2[c];
        float4 v = out[i];
        v.x = fmaxf(0.f, fmaf(a, v.x, bb));
        v.y = fmaxf(0.f, fmaf(a, v.y, bb));
        v.z = fmaxf(0.f, fmaf(a, v.z, bb));
        v.w = fmaxf(0.f, fmaf(a, v.w, bb));
        out[i] = v;
    }
}

// ---------------- launcher (harness pointers ONLY as kernel args) ----------------
extern "C" void kernel_launch(void* const* d_in, const int* in_sizes, int n_in,
                              void* d_out, int out_size)
{
    const float* x      = (const float*)d_in[0];
    const float* cw     = (const float*)d_in[1];
    const float* w1     = (const float*)d_in[2];
    const float* w2     = (const float*)d_in[3];
    const float* gamma1 = (const float*)d_in[4];
    const float* beta1  = (const float*)d_in[5];
    const float* gamma2 = (const float*)d_in[6];
    const float* beta2  = (const float*)d_in[7];
    float* out = (float*)d_out;

    zero_stats_kernel<<<1, 128>>>();
    zero_border_kernel<<<33, 256>>>();
    wprep_sh_kernel<64, 1><<<16, 256>>>(w1);
    wprep_sh_kernel<128, 2><<<32, 256>>>(w2);
    wprep_dy_kernel<64, 0, 1><<<8192, 256>>>(cw);
    wprep_dy_kernel<128, WOFF2, 2><<<16384, 256>>>(cw);

    // layer 1
    xsplit_kernel<64, 1><<<8192, 256>>>(x);
    conv_mma_kernel<64, 1><<<4096, 256>>>(nullptr);
    finalize_stats_kernel<<<1, 128>>>(gamma1, beta1, 1);

    // layer 2 (BN1+ReLU fused into xsplit)
    xsplit_kernel<128, 2><<<8192, 256>>>(nullptr);
    conv_mma_kernel<128, 2><<<4096, 256>>>(out);
    finalize_stats_kernel<<<1, 128>>>(gamma2, beta2, 2);

    apply_bn2_kernel<<<8192, 256>>>((float4*)out);
}

// round 13
// speedup vs baseline: 3.6882x; 1.2486x over previous
#include <cuda_runtime.h>
#include <cuda_bf16.h>
#include <cstdint>

#define BATCH 8
#define EPSBN 1e-5f
#define ABLK  110592
#define WOFF2 36864
#define PW    258            // padded width (1-px halo each side)

// ---------------- scratch globals (all referenced ONLY in device code) ----------
__device__ float g_y1[(size_t)8 * 128 * 256 * 256];            // 256 MB
__device__ float g_sum1[128], g_sqs1[128], g_sum2[128], g_sqs2[128];
__device__ float g_a1[128], g_b1[128], g_a2[128], g_b2[128];

// padded split activations [b][y+1][x+1][ci] bf16
__device__ __align__(16) __nv_bfloat16 g_x1hi[(size_t)8 * PW * PW * 64];
__device__ __align__(16) __nv_bfloat16 g_x1lo[(size_t)8 * PW * PW * 64];
__device__ __align__(16) __nv_bfloat16 g_x2hi[(size_t)8 * PW * PW * 128];
__device__ __align__(16) __nv_bfloat16 g_x2lo[(size_t)8 * PW * PW * 128];
// weight tiles, k-chunk 16: [(k*NS)+sub][64 oc][16 ci]
__device__ __align__(16) __nv_bfloat16 g_wsh1hi[36 * 1024], g_wsh1lo[36 * 1024];
__device__ __align__(16) __nv_bfloat16 g_wsh2hi[72 * 1024], g_wsh2lo[72 * 1024];
__device__ __align__(16) __nv_bfloat16 g_wdy1hi[(size_t)512 * 36 * 1024];
__device__ __align__(16) __nv_bfloat16 g_wdy1lo[(size_t)512 * 36 * 1024];
__device__ __align__(16) __nv_bfloat16 g_wdy2hi[(size_t)512 * 72 * 1024];
__device__ __align__(16) __nv_bfloat16 g_wdy2lo[(size_t)512 * 72 * 1024];

// ---------------- helpers -------------------------------------------------------
__device__ __forceinline__ uint32_t smem_u32(const void* p) {
    uint32_t a;
    asm("{ .reg .u64 t; cvta.to.shared.u64 t, %1; cvt.u32.u64 %0, t; }"
        : "=r"(a) : "l"(p));
    return a;
}
#define LDM4(r, a) \
    asm volatile("ldmatrix.sync.aligned.m8n8.x4.shared.b16 {%0,%1,%2,%3}, [%4];" \
                 : "=r"((r)[0]), "=r"((r)[1]), "=r"((r)[2]), "=r"((r)[3]) : "r"(a))
#define MMA(d, a, b0, b1) \
    asm volatile("mma.sync.aligned.m16n8k16.row.col.f32.bf16.bf16.f32 " \
                 "{%0,%1,%2,%3},{%4,%5,%6,%7},{%8,%9},{%0,%1,%2,%3};" \
                 : "+f"((d)[0]), "+f"((d)[1]), "+f"((d)[2]), "+f"((d)[3]) \
                 : "r"((a)[0]), "r"((a)[1]), "r"((a)[2]), "r"((a)[3]), "r"(b0), "r"(b1))

__device__ __forceinline__ uint32_t pkbf(float lo, float hi) {
    return (uint32_t)__bfloat16_as_ushort(__float2bfloat16(lo)) |
           ((uint32_t)__bfloat16_as_ushort(__float2bfloat16(hi)) << 16);
}

// double-buffered static smem: per buffer A_HI/A_LO/W_HI/W_LO, 128 rows x 48B each
static constexpr int S_ALO = 6144;
static constexpr int S_WHI = 12288;
static constexpr int S_WLO = 18432;
static constexpr int S_BUF = 24576;
static constexpr int SMEM_TOTAL = 49152;   // exactly 48KB static

// ---------------- small kernels -------------------------------------------------
__global__ void zero_stats_kernel() {
    int t = threadIdx.x;
    if (t < 128) { g_sum1[t] = 0.f; g_sqs1[t] = 0.f; g_sum2[t] = 0.f; g_sqs2[t] = 0.f; }
}

__global__ void zero_border_kernel() {
    int idx = blockIdx.x * 256 + threadIdx.x;
    if (idx >= 8 * 1028) return;
    int b = idx / 1028, s = idx % 1028;
    int y, x;
    if (s < 258)      { y = 0;           x = s; }
    else if (s < 516) { y = 257;         x = s - 258; }
    else if (s < 772) { y = s - 516 + 1; x = 0; }
    else              { y = s - 772 + 1; x = 257; }
    size_t p = ((size_t)b * PW + y) * PW + x;
    uint4 z = make_uint4(0, 0, 0, 0);
    uint4* h1 = (uint4*)(g_x1hi + p * 64);
    uint4* l1 = (uint4*)(g_x1lo + p * 64);
    #pragma unroll
    for (int i = 0; i < 8; ++i) { h1[i] = z; l1[i] = z; }
    uint4* h2 = (uint4*)(g_x2hi + p * 128);
    uint4* l2 = (uint4*)(g_x2lo + p * 128);
    #pragma unroll
    for (int i = 0; i < 16; ++i) { h2[i] = z; l2[i] = z; }
}

// x -> padded [b][y+1][x+1][ci] bf16 hi/lo; layer 2 applies BN1+ReLU
template<int CIN, int LAYER>
__global__ void xsplit_kernel(const float* __restrict__ xin)
{
    __shared__ float tile[CIN][65];
    const int blk = blockIdx.x;
    const int xb = blk & 3, y = (blk >> 2) & 255, b = blk >> 10;
    const int tid = threadIdx.x;
    const float* src = (LAYER == 1) ? xin : (const float*)g_y1;
    __nv_bfloat16* dhi = (LAYER == 1) ? g_x1hi : g_x2hi;
    __nv_bfloat16* dlo = (LAYER == 1) ? g_x1lo : g_x2lo;

    for (int i = tid; i < CIN * 64; i += 256) {
        int c = i >> 6, x = i & 63;
        float v = src[(((size_t)(b * CIN + c)) << 16) + (y << 8) + (xb << 6) + x];
        if (LAYER == 2) v = fmaxf(0.f, fmaf(g_a1[c], v, g_b1[c]));
        tile[c][x] = v;
    }
    __syncthreads();

    const int GSH = (CIN == 64) ? 3 : 4;
    const int GP  = CIN / 8;
    for (int i = tid; i < 64 * GP; i += 256) {
        int x = i >> GSH, g = i & (GP - 1);
        float v[8], hv[8];
        #pragma unroll
        for (int j = 0; j < 8; ++j) {
            v[j]  = tile[g * 8 + j][x];
            hv[j] = __bfloat162float(__float2bfloat16(v[j]));
        }
        uint4 uh, ul;
        uh.x = pkbf(hv[0], hv[1]); uh.y = pkbf(hv[2], hv[3]);
        uh.z = pkbf(hv[4], hv[5]); uh.w = pkbf(hv[6], hv[7]);
        ul.x = pkbf(v[0] - hv[0], v[1] - hv[1]); ul.y = pkbf(v[2] - hv[2], v[3] - hv[3]);
        ul.z = pkbf(v[4] - hv[4], v[5] - hv[5]); ul.w = pkbf(v[6] - hv[6], v[7] - hv[7]);
        size_t off = (((size_t)b * PW + (y + 1)) * PW + (xb * 64 + x + 1)) * CIN + g * 8;
        *(uint4*)((char*)dhi + off * 2) = uh;
        *(uint4*)((char*)dlo + off * 2) = ul;
    }
}

// shared weights [64oc][CIN][9] -> tiles [k*NS+sub][64][16]
template<int CIN, int LAYER>
__global__ void wprep_sh_kernel(const float* __restrict__ wsh)
{
    int idx = blockIdx.x * 256 + threadIdx.x;
    if (idx >= 64 * CIN) return;
    int ci = idx & (CIN - 1);
    int oc = idx >> ((CIN == 64) ? 6 : 7);
    constexpr int NS = CIN / 16;
    int sub = ci >> 4, cl = ci & 15;
    const float* s = wsh + ((size_t)oc * CIN + ci) * 9;
    __nv_bfloat16* hi = (LAYER == 1) ? g_wsh1hi : g_wsh2hi;
    __nv_bfloat16* lo = (LAYER == 1) ? g_wsh1lo : g_wsh2lo;
    #pragma unroll
    for (int k = 0; k < 9; ++k) {
        float v = s[k];
        __nv_bfloat16 hb = __float2bfloat16(v);
        size_t off = (size_t)(k * NS + sub) * 1024 + oc * 16 + cl;
        hi[off] = hb;
        lo[off] = __float2bfloat16(v - __bfloat162float(hb));
    }
}

// dynamic weights -> tiles [bp][k*NS+sub][64][16]
template<int CIN, int WOFF, int LAYER>
__global__ void wprep_dy_kernel(const float* __restrict__ cw)
{
    const long long idx = (long long)blockIdx.x * 256 + threadIdx.x;
    constexpr int LC = (CIN == 64) ? 6 : 7;
    const int ci = (int)(idx & (CIN - 1));
    const int oc = (int)((idx >> LC) & 63);
    const int bp = (int)(idx >> (LC + 6));
    constexpr int NS = CIN / 16;
    const int sub = ci >> 4, cl = ci & 15;
    const float* s = cw + (size_t)bp * ABLK + WOFF + ((size_t)oc * CIN + ci) * 9;
    __nv_bfloat16* hi = (LAYER == 1) ? g_wdy1hi : g_wdy2hi;
    __nv_bfloat16* lo = (LAYER == 1) ? g_wdy1lo : g_wdy2lo;
    #pragma unroll
    for (int k = 0; k < 9; ++k) {
        float v = s[k];
        __nv_bfloat16 hb = __float2bfloat16(v);
        size_t off = ((size_t)bp * (9 * NS) + k * NS + sub) * 1024 + oc * 16 + cl;
        hi[off] = hb;
        lo[off] = __float2bfloat16(v - __bfloat162float(hb));
    }
}

// ---------------- main conv: bf16-split warp-MMA, smem-double-buffered -----------
// CTA = (b, patch, 4-row quad). D[128 px][128 oc]; 8 warps x (64px x 32oc).
// One __syncthreads per chunk; ldmatrix fragment loads.
template<int CIN, int LAYER>
__global__ void __launch_bounds__(256, 2)
conv_mma_kernel(float* __restrict__ dout)
{
    __shared__ __align__(16) unsigned char sm[SMEM_TOTAL];
    const uint32_t sbase = smem_u32(sm);
    const int tid = threadIdx.x, lane = tid & 31, wid = tid >> 5;
    const int wm = wid & 1, wn = wid >> 1;

    const __nv_bfloat16* xhi = (LAYER == 1) ? g_x1hi : g_x2hi;
    const __nv_bfloat16* xlo = (LAYER == 1) ? g_x1lo : g_x2lo;
    const __nv_bfloat16* wshhi = (LAYER == 1) ? g_wsh1hi : g_wsh2hi;
    const __nv_bfloat16* wshlo = (LAYER == 1) ? g_wsh1lo : g_wsh2lo;
    const __nv_bfloat16* wdyhi = (LAYER == 1) ? g_wdy1hi : g_wdy2hi;
    const __nv_bfloat16* wdylo = (LAYER == 1) ? g_wdy1lo : g_wdy2lo;
    float* dst = (LAYER == 1) ? (float*)g_y1 : dout;

    const int blk = blockIdx.x;
    const int b = blk >> 9, p = (blk >> 3) & 63, q = blk & 7;
    const int y0 = ((p >> 3) << 5) + (q << 2);
    const int x0 = (p & 7) << 5;
    const int bp = b * 64 + p;
    constexpr int NS = CIN / 16;
    constexpr int NC = 9 * NS;

    float d[4][4][4];
    #pragma unroll
    for (int i = 0; i < 4; ++i)
        #pragma unroll
        for (int j = 0; j < 4; ++j)
            #pragma unroll
            for (int k = 0; k < 4; ++k) d[i][j][k] = 0.f;

    // ldmatrix lane addresses (row stride 48B)
    const uint32_t laneA = (uint32_t)(lane & 15) * 48 + (uint32_t)(lane >> 4) * 16;
    const uint32_t laneW = (uint32_t)((lane & 7) + ((lane >> 4) << 3)) * 48 +
                           (uint32_t)((lane >> 3) & 1) * 16;

    const int px = tid >> 1, seg = tid & 1;    // A row / 16B seg
    const int wrow = tid >> 1;                 // W row

    uint4 pfA[2], pfW[2];

    auto prefetch = [&](int cc) {
        const int tap = cc / NS, sub = cc - tap * NS;
        const int ky = tap / 3, kx = tap - ky * 3;
        const int y = y0 + (px >> 5) + ky;
        const int x = x0 + (px & 31) + kx;
        const size_t aoff = (((size_t)b * PW + y) * PW + x) * CIN + sub * 16 + seg * 8;
        pfA[0] = *(const uint4*)(xhi + aoff);
        pfA[1] = *(const uint4*)(xlo + aoff);
        if (wrow < 64) {
            const size_t woff = (size_t)cc * 1024 + wrow * 16 + seg * 8;
            pfW[0] = *(const uint4*)(wshhi + woff);
            pfW[1] = *(const uint4*)(wshlo + woff);
        } else {
            const size_t woff = ((size_t)bp * NC + cc) * 1024 + (wrow - 64) * 16 + seg * 8;
            pfW[0] = *(const uint4*)(wdyhi + woff);
            pfW[1] = *(const uint4*)(wdylo + woff);
        }
    };
    auto sts = [&](int buf) {
        unsigned char* bb = sm + buf * S_BUF;
        *(uint4*)(bb + px * 48 + seg * 16)          = pfA[0];
        *(uint4*)(bb + S_ALO + px * 48 + seg * 16)  = pfA[1];
        *(uint4*)(bb + S_WHI + wrow * 48 + seg * 16) = pfW[0];
        *(uint4*)(bb + S_WLO + wrow * 48 + seg * 16) = pfW[1];
    };

    prefetch(0);
    sts(0);
    if (NC > 1) prefetch(1);
    __syncthreads();

    for (int cc = 0; cc < NC; ++cc) {
        const int buf = cc & 1;
        // ---- compute: D += Ah*Wh + Ah*Wl + Al*Wh ----
        const uint32_t bufb = sbase + buf * S_BUF;
        const uint32_t Ah = bufb + wm * 3072 + laneA;
        const uint32_t Al = Ah + S_ALO;
        const uint32_t Wh = bufb + S_WHI + wn * 1536 + laneW;
        const uint32_t Wl = Wh + 6144;
        uint32_t a[4][4], w[2][4], v[2][4];
        #pragma unroll
        for (int mf = 0; mf < 4; ++mf) LDM4(a[mf], Ah + mf * 768);
        #pragma unroll
        for (int nf = 0; nf < 2; ++nf) LDM4(w[nf], Wh + nf * 768);
        #pragma unroll
        for (int mf = 0; mf < 4; ++mf)
            #pragma unroll
            for (int nf = 0; nf < 2; ++nf) {
                MMA(d[mf][nf * 2],     a[mf], w[nf][0], w[nf][1]);
                MMA(d[mf][nf * 2 + 1], a[mf], w[nf][2], w[nf][3]);
            }
        #pragma unroll
        for (int nf = 0; nf < 2; ++nf) LDM4(v[nf], Wl + nf * 768);
        #pragma unroll
        for (int mf = 0; mf < 4; ++mf)
            #pragma unroll
            for (int nf = 0; nf < 2; ++nf) {
                MMA(d[mf][nf * 2],     a[mf], v[nf][0], v[nf][1]);
                MMA(d[mf][nf * 2 + 1], a[mf], v[nf][2], v[nf][3]);
            }
        #pragma unroll
        for (int mf = 0; mf < 4; ++mf) LDM4(a[mf], Al + mf * 768);
        #pragma unroll
        for (int mf = 0; mf < 4; ++mf)
            #pragma unroll
            for (int nf = 0; nf < 2; ++nf) {
                MMA(d[mf][nf * 2],     a[mf], w[nf][0], w[nf][1]);
                MMA(d[mf][nf * 2 + 1], a[mf], w[nf][2], w[nf][3]);
            }
        // ---- fill other buffer for next chunk, start LDG for chunk+2 ----
        if (cc + 1 < NC) {
            sts(buf ^ 1);
            if (cc + 2 < NC) prefetch(cc + 2);
            __syncthreads();
        }
    }

    // ---- epilogue: store + fused BN stats ----
    float* gsum = (LAYER == 1) ? g_sum1 : g_sum2;
    float* gsqs = (LAYER == 1) ? g_sqs1 : g_sqs2;
    const int r4 = lane >> 2;
    const int c2 = (lane & 3) << 1;
    #pragma unroll
    for (int mf = 0; mf < 4; ++mf) {
        int pxA = wm * 64 + mf * 16 + r4;
        int pxB = pxA + 8;
        size_t pixA = (size_t)(y0 + (pxA >> 5)) * 256 + x0 + (pxA & 31);
        size_t pixB = (size_t)(y0 + (pxB >> 5)) * 256 + x0 + (pxB & 31);
        #pragma unroll
        for (int n8 = 0; n8 < 4; ++n8) {
            int oc = wn * 32 + n8 * 8 + c2;
            size_t base = ((size_t)(b * 128 + oc)) << 16;
            dst[base + pixA]         = d[mf][n8][0];
            dst[base + 65536 + pixA] = d[mf][n8][1];
            dst[base + pixB]         = d[mf][n8][2];
            dst[base + 65536 + pixB] = d[mf][n8][3];
        }
    }
    #pragma unroll
    for (int n8 = 0; n8 < 4; ++n8) {
        float sA = 0.f, qA = 0.f, sB = 0.f, qB = 0.f;
        #pragma unroll
        for (int mf = 0; mf < 4; ++mf) {
            float e0 = d[mf][n8][0], e1 = d[mf][n8][1];
            float e2 = d[mf][n8][2], e3 = d[mf][n8][3];
            sA += e0 + e2; qA = fmaf(e0, e0, fmaf(e2, e2, qA));
            sB += e1 + e3; qB = fmaf(e1, e1, fmaf(e3, e3, qB));
        }
        #pragma unroll
        for (int off = 16; off >= 4; off >>= 1) {
            sA += __shfl_down_sync(0xffffffffu, sA, off);
            qA += __shfl_down_sync(0xffffffffu, qA, off);
            sB += __shfl_down_sync(0xffffffffu, sB, off);
            qB += __shfl_down_sync(0xffffffffu, qB, off);
        }
        if (lane < 4) {
            int oc = wn * 32 + n8 * 8 + c2;
            atomicAdd(&gsum[oc], sA);     atomicAdd(&gsqs[oc], qA);
            atomicAdd(&gsum[oc + 1], sB); atomicAdd(&gsqs[oc + 1], qB);
        }
    }
}

// ---------------- BN finalize / apply -------------------------------------------
__global__ void finalize_stats_kernel(const float* __restrict__ gamma,
                                      const float* __restrict__ beta, int layer)
{
    int c = threadIdx.x;
    if (c >= 128) return;
    const float invN = 1.f / (float)((size_t)BATCH * 256 * 256);
    float s = (layer == 1) ? g_sum1[c] : g_sum2[c];
    float q = (layer == 1) ? g_sqs1[c] : g_sqs2[c];
    float m = s * invN;
    float var = fmaf(-m, m, q * invN);
    float inv = rsqrtf(var + EPSBN);
    float a = gamma[c] * inv;
    float bb = fmaf(-a, m, beta[c]);
    if (layer == 1) { g_a1[c] = a; g_b1[c] = bb; }
    else            { g_a2[c] = a; g_b2[c] = bb; }
}

__global__ void apply_bn2_kernel(float4* __restrict__ out)
{
    const size_t n4 = (size_t)BATCH * 128 * 256 * 256 / 4;
    for (size_t i = (size_t)blockIdx.x * blockDim.x + threadIdx.x; i < n4;
         i += (size_t)gridDim.x * blockDim.x) {
        int c = (int)((i >> 14) & 127);
        float a = g_a2[c], bb = g_b2[c];
        float4 v = out[i];
        v.x = fmaxf(0.f, fmaf(a, v.x, bb));
        v.y = fmaxf(0.f, fmaf(a, v.y, bb));
        v.z = fmaxf(0.f, fmaf(a, v.z, bb));
        v.w = fmaxf(0.f, fmaf(a, v.w, bb));
        out[i] = v;
    }
}

// ---------------- launcher (harness pointers ONLY as kernel args) ----------------
extern "C" void kernel_launch(void* const* d_in, const int* in_sizes, int n_in,
                              void* d_out, int out_size)
{
    const float* x      = (const float*)d_in[0];
    const float* cw     = (const float*)d_in[1];
    const float* w1     = (const float*)d_in[2];
    const float* w2     = (const float*)d_in[3];
    const float* gamma1 = (const float*)d_in[4];
    const float* beta1  = (const float*)d_in[5];
    const float* gamma2 = (const float*)d_in[6];
    const float* beta2  = (const float*)d_in[7];
    float* out = (float*)d_out;

    zero_stats_kernel<<<1, 128>>>();
    zero_border_kernel<<<33, 256>>>();
    wprep_sh_kernel<64, 1><<<16, 256>>>(w1);
    wprep_sh_kernel<128, 2><<<32, 256>>>(w2);
    wprep_dy_kernel<64, 0, 1><<<8192, 256>>>(cw);
    wprep_dy_kernel<128, WOFF2, 2><<<16384, 256>>>(cw);

    // layer 1
    xsplit_kernel<64, 1><<<8192, 256>>>(x);
    conv_mma_kernel<64, 1><<<4096, 256>>>(nullptr);
    finalize_stats_kernel<<<1, 128>>>(gamma1, beta1, 1);

    // layer 2 (BN1+ReLU fused into xsplit)
    xsplit_kernel<128, 2><<<8192, 256>>>(nullptr);
    conv_mma_kernel<128, 2><<<4096, 256>>>(out);
    finalize_stats_kernel<<<1, 128>>>(gamma2, beta2, 2);

    apply_bn2_kernel<<<8192, 256>>>((float4*)out);
}